// round 4
// baseline (speedup 1.0000x reference)
#include <cuda_runtime.h>
#include <math.h>

#define B_    128
#define TP2   2050
#define T_    2049
#define H_    64
#define G7    448     // 7*H real gates
#define G8    512     // padded: 8 gate slots per hidden unit
#define K_    100
#define KE    103     // K+3 rows in in_emb
#define NTHR  608     // 512 matvec + 96 out-proj (19 warps)

// Remapped input-projection table: pretab2[e][j*8+x] = in_emb[e]@Wx[:,x*64+j] + b   (x<7)
__device__ float g_pretab2[KE * G8];

__global__ void build_pretab(const float* __restrict__ in_emb,
                             const float* __restrict__ Wx,
                             const float* __restrict__ bias) {
    int e = blockIdx.x;
    int t = threadIdx.x;            // 0..511
    int x = t & 7, j = t >> 3;
    float s = 0.f;
    if (x < 7) {
        int g = x * H_ + j;
        s = bias[g];
#pragma unroll
        for (int k = 0; k < H_; ++k)
            s = fmaf(in_emb[e * H_ + k], Wx[k * G7 + g], s);
    }
    g_pretab2[e * G8 + t] = s;
}

// ---- packed f32x2 helpers ----
typedef unsigned long long u64;
__device__ __forceinline__ u64 pack2(float x, float y) {
    u64 r; asm("mov.b64 %0, {%1, %2};" : "=l"(r) : "f"(x), "f"(y)); return r;
}
__device__ __forceinline__ float2 unpack2(u64 v) {
    float2 r; asm("mov.b64 {%0, %1}, %2;" : "=f"(r.x), "=f"(r.y) : "l"(v)); return r;
}
__device__ __forceinline__ u64 ffma2_(u64 a, u64 b, u64 c) {
    u64 d; asm("fma.rn.f32x2 %0, %1, %2, %3;" : "=l"(d) : "l"(a), "l"(b), "l"(c));
    return d;
}
__device__ __forceinline__ u64 fadd2_(u64 a, u64 b) {
    u64 d; asm("add.rn.f32x2 %0, %1, %2;" : "=l"(d) : "l"(a), "l"(b));
    return d;
}

__device__ __forceinline__ float fast_tanh(float x) {
    float e = __expf(-2.0f * x);
    return __fdividef(2.0f, 1.0f + e) - 1.0f;
}
__device__ __forceinline__ float fast_softplus(float x) {
    float e = __expf(-fabsf(x));
    return fmaxf(x, 0.f) + __logf(1.0f + e);
}

__global__ void __launch_bounds__(NTHR, 1)
scan_kernel(const int*   __restrict__ event_t,
            const float* __restrict__ dtime_t,
            const float* __restrict__ Wh,
            const float* __restrict__ out_emb,
            float*       __restrict__ out) {
    extern __shared__ float smem[];
    float* pretab_s = smem;                 // KE*G8 floats (206 KB)
    float* h_s      = pretab_s + KE * G8;   // 2*H floats (double buffered, 16B aligned)

    const int tid  = threadIdx.x;
    const int bb   = blockIdx.x;
    const int lane = tid & 31;

    const int*   ev_row  = event_t + bb * TP2;
    const float* dt_row  = dtime_t + bb * TP2;
    float*       out_row = out + (size_t)bb * T_ * K_;

    // ---- Stage remapped PreTable into shared memory ----
    for (int i = tid; i < KE * G8; i += NTHR) pretab_s[i] = g_pretab2[i];
    if (tid < H_) h_s[H_ + tid] = 0.f;       // h_{-1} lives in buf1

    if (tid < G8) {
        // ================= matvec / update threads =================
        const int x = tid & 7;               // gate slot (7 = dummy)
        const int j = tid >> 3;              // hidden unit
        const int base = lane & ~7;          // lane of x==0 for this unit

        // Register-resident Wh column for gate g = x*64 + j (zeros for x==7)
        u64 wr2[H_ / 2];
        if (x < 7) {
            const int g = x * H_ + j;
#pragma unroll
            for (int k2 = 0; k2 < H_ / 2; ++k2)
                wr2[k2] = pack2(Wh[(2 * k2) * G7 + g], Wh[(2 * k2 + 1) * G7 + g]);
        } else {
#pragma unroll
            for (int k2 = 0; k2 < H_ / 2; ++k2) wr2[k2] = 0ull;
        }

        float c = 0.f, cbv = 0.f;            // valid in x==0 lanes
        const float kmul = (x == 2) ? -2.0f : -1.0f;
        const float bnum = (x == 2) ?  2.0f :  1.0f;
        const float aoff = (x == 2) ? -1.0f :  0.0f;

        __syncthreads();

        int   ev  = ev_row[0];
        float dtv = dt_row[1];

        for (int t = 0; t < T_; ++t) {
            const int   ev_next = ev_row[(t + 1 < T_) ? (t + 1) : (T_ - 1)];
            const float dt_next = dt_row[(t + 2 < TP2) ? (t + 2) : (TP2 - 1)];

            const float* hr = h_s + (((t & 1) ^ 1) ? H_ : 0);   // h_{t-1}
            float*       hw = h_s + ((t & 1) ? H_ : 0);         // h_t

            // ---- g = pre[ev] + h_{t-1} @ Wh (f32x2, 4 chains) ----
            const ulonglong2* h2 = (const ulonglong2*)hr;
            u64 a0 = pack2(pretab_s[ev * G8 + tid], 0.f);
            u64 a1 = 0ull, a2 = 0ull, a3 = 0ull;
#pragma unroll
            for (int k4 = 0; k4 < 16; k4 += 2) {
                ulonglong2 hp = h2[k4];
                a0 = ffma2_(hp.x, wr2[2 * k4],     a0);
                a1 = ffma2_(hp.y, wr2[2 * k4 + 1], a1);
                ulonglong2 hq = h2[k4 + 1];
                a2 = ffma2_(hq.x, wr2[2 * k4 + 2], a2);
                a3 = ffma2_(hq.y, wr2[2 * k4 + 3], a3);
            }
            float2 r = unpack2(fadd2_(fadd2_(a0, a1), fadd2_(a2, a3)));
            const float g = r.x + r.y;

            // ---- activation (uniform sigmoid/tanh form; delta lane predicated) ----
            float a = __fdividef(bnum, 1.0f + __expf(kmul * g)) + aoff;
            if (x == 6) a = __expf(-dtv * fast_softplus(g));   // exp(-delta*dt)

            // ---- in-warp gather of the 7 gate values of unit j ----
            const float iv  = __shfl_sync(0xffffffffu, a, base + 0);
            const float fv  = __shfl_sync(0xffffffffu, a, base + 1);
            const float zv  = __shfl_sync(0xffffffffu, a, base + 2);
            const float ov  = __shfl_sync(0xffffffffu, a, base + 3);
            const float ibv = __shfl_sync(0xffffffffu, a, base + 4);
            const float fbv = __shfl_sync(0xffffffffu, a, base + 5);
            const float ev_ = __shfl_sync(0xffffffffu, a, base + 6);

            // ---- cell update (meaningful in x==0 lanes; others compute garbage) ----
            const float ci  = fmaf(fv, c, iv * zv);
            const float cbi = fmaf(fbv, cbv, ibv * zv);
            const float cn  = fmaf(ci - cbi, ev_, cbi);
            c   = cn;
            cbv = cbi;
            const float hn = ov * fast_tanh(cn);
            if (x == 0) hw[j] = hn;

            __syncthreads();
            ev  = ev_next;
            dtv = dt_next;
        }
    } else {
        // ================= out-proj threads (tid 512..607) =================
        const int ot = tid - G8;             // 0..95
        u64 oe2[H_ / 2];
#pragma unroll
        for (int i = 0; i < H_ / 2; ++i)
            oe2[i] = pack2(out_emb[ot * H_ + 2 * i], out_emb[ot * H_ + 2 * i + 1]);
        const float4* oe_x = (ot < 4) ? (const float4*)(out_emb + (96 + ot) * H_)
                                      : (const float4*)out_emb;

        __syncthreads();

        for (int t = 0; t < T_; ++t) {
            const float* hr = h_s + (((t & 1) ^ 1) ? H_ : 0);   // h_{t-1}

            if (t > 0) {
                const ulonglong2* hp2 = (const ulonglong2*)hr;
                u64 s0 = 0ull, s1 = 0ull, s2 = 0ull, s3 = 0ull;
#pragma unroll
                for (int i = 0; i < 16; i += 2) {
                    ulonglong2 hv = hp2[i];
                    s0 = ffma2_(hv.x, oe2[2 * i],     s0);
                    s1 = ffma2_(hv.y, oe2[2 * i + 1], s1);
                    ulonglong2 hu = hp2[i + 1];
                    s2 = ffma2_(hu.x, oe2[2 * i + 2], s2);
                    s3 = ffma2_(hu.y, oe2[2 * i + 3], s3);
                }
                float2 sr = unpack2(fadd2_(fadd2_(s0, s1), fadd2_(s2, s3)));
                out_row[(size_t)(t - 1) * K_ + ot] = fast_softplus(sr.x + sr.y);

                if (ot < 4) {                 // logits 96..99 via L1-resident LDG
                    float s = 0.f;
                    const float4* hf = (const float4*)hr;
#pragma unroll
                    for (int i = 0; i < 16; ++i) {
                        float4 w = __ldg(oe_x + i);
                        float4 h = hf[i];
                        s = fmaf(h.x, w.x, s); s = fmaf(h.y, w.y, s);
                        s = fmaf(h.z, w.z, s); s = fmaf(h.w, w.w, s);
                    }
                    out_row[(size_t)(t - 1) * K_ + 96 + ot] = fast_softplus(s);
                }
            }
            __syncthreads();
        }

        // ---- drain: final output row from h_{T-1} (buf0, since (T-1)&1==0) ----
        const float* hl = h_s;
        const ulonglong2* hp2 = (const ulonglong2*)hl;
        u64 s0 = 0ull, s1 = 0ull;
#pragma unroll
        for (int i = 0; i < 16; ++i) {
            ulonglong2 hv = hp2[i];
            s0 = ffma2_(hv.x, oe2[2 * i],     s0);
            s1 = ffma2_(hv.y, oe2[2 * i + 1], s1);
        }
        float2 sr = unpack2(fadd2_(s0, s1));
        out_row[(size_t)(T_ - 1) * K_ + ot] = fast_softplus(sr.x + sr.y);
        if (ot < 4) {
            float s = 0.f;
            const float4* hf = (const float4*)hl;
#pragma unroll
            for (int i = 0; i < 16; ++i) {
                float4 w = __ldg(oe_x + i);
                float4 h = hf[i];
                s = fmaf(h.x, w.x, s); s = fmaf(h.y, w.y, s);
                s = fmaf(h.z, w.z, s); s = fmaf(h.w, w.w, s);
            }
            out_row[(size_t)(T_ - 1) * K_ + 96 + ot] = fast_softplus(s);
        }
    }
}

extern "C" void kernel_launch(void* const* d_in, const int* in_sizes, int n_in,
                              void* d_out, int out_size) {
    const int*   ev   = (const int*)  d_in[0];
    const float* dt   = (const float*)d_in[1];
    const float* iemb = (const float*)d_in[2];
    const float* Wx   = (const float*)d_in[3];
    const float* Wh   = (const float*)d_in[4];
    const float* bias = (const float*)d_in[5];
    const float* oemb = (const float*)d_in[6];
    float* out = (float*)d_out;

    const size_t smem_bytes = (size_t)(KE * G8 + 2 * H_ + 16) * sizeof(float);
    cudaFuncSetAttribute(scan_kernel, cudaFuncAttributeMaxDynamicSharedMemorySize,
                         (int)smem_bytes);

    build_pretab<<<KE, G8>>>(iemb, Wx, bias);
    scan_kernel<<<B_, NTHR, smem_bytes>>>(ev, dt, Wh, oemb, out);
}

// round 5
// speedup vs baseline: 1.4607x; 1.4607x over previous
#include <cuda_runtime.h>
#include <math.h>

#define B_    128
#define TP2   2050
#define T_    2049
#define H_    64
#define G7    448     // 7*H real gates
#define K_    100
#define KE    103     // K+3 rows in in_emb
#define MVT   256     // matvec threads: 4 per hidden unit (y=0..3), 2 gates each
#define NTHR  320     // 256 matvec + 64 out-proj (10 warps)

// Packed input-projection table: pre2[e][tid] = {pre(gate y*64+j), pre(gate (y+4)*64+j)}
// where j = tid>>2, y = tid&3 (hi slot zero for y==3).
__device__ float2 g_pretab2[KE * MVT];

__global__ void build_pretab(const float* __restrict__ in_emb,
                             const float* __restrict__ Wx,
                             const float* __restrict__ bias) {
    int e = blockIdx.x;
    int t = threadIdx.x;            // 0..255
    int j = t >> 2, y = t & 3;
    int glo = y * H_ + j;
    float lo = bias[glo];
#pragma unroll
    for (int k = 0; k < H_; ++k)
        lo = fmaf(in_emb[e * H_ + k], Wx[k * G7 + glo], lo);
    float hi = 0.f;
    if (y < 3) {
        int ghi = (y + 4) * H_ + j;
        hi = bias[ghi];
#pragma unroll
        for (int k = 0; k < H_; ++k)
            hi = fmaf(in_emb[e * H_ + k], Wx[k * G7 + ghi], hi);
    }
    g_pretab2[e * MVT + t] = make_float2(lo, hi);
}

// ---- packed f32x2 helpers ----
typedef unsigned long long u64;
__device__ __forceinline__ u64 pack2(float x, float y) {
    u64 r; asm("mov.b64 %0, {%1, %2};" : "=l"(r) : "f"(x), "f"(y)); return r;
}
__device__ __forceinline__ float2 unpack2(u64 v) {
    float2 r; asm("mov.b64 {%0, %1}, %2;" : "=f"(r.x), "=f"(r.y) : "l"(v)); return r;
}
__device__ __forceinline__ u64 ffma2_(u64 a, u64 b, u64 c) {
    u64 d; asm("fma.rn.f32x2 %0, %1, %2, %3;" : "=l"(d) : "l"(a), "l"(b), "l"(c));
    return d;
}
__device__ __forceinline__ u64 fadd2_(u64 a, u64 b) {
    u64 d; asm("add.rn.f32x2 %0, %1, %2;" : "=l"(d) : "l"(a), "l"(b));
    return d;
}

__device__ __forceinline__ float fast_tanh(float x) {
    float e = __expf(-2.0f * x);
    return __fdividef(2.0f, 1.0f + e) - 1.0f;
}
__device__ __forceinline__ float fast_softplus(float x) {
    float e = __expf(-fabsf(x));
    return fmaxf(x, 0.f) + __logf(1.0f + e);
}

__global__ void __launch_bounds__(NTHR, 1)
scan_kernel(const int*   __restrict__ event_t,
            const float* __restrict__ dtime_t,
            const float* __restrict__ Wh,
            const float* __restrict__ out_emb,
            float*       __restrict__ out) {
    extern __shared__ float smem[];
    float2* pretab_s = (float2*)smem;                  // KE*MVT float2 (206 KB)
    float*  h_s      = smem + 2 * KE * MVT;            // 2*H floats (double buffered)

    const int tid  = threadIdx.x;
    const int bb   = blockIdx.x;
    const int lane = tid & 31;

    const int*   ev_row  = event_t + bb * TP2;
    const float* dt_row  = dtime_t + bb * TP2;
    float*       out_row = out + (size_t)bb * T_ * K_;

    // ---- Stage packed PreTable into shared memory ----
    {
        const float4* src = (const float4*)g_pretab2;
        float4*       dst = (float4*)pretab_s;
        for (int i = tid; i < KE * MVT / 2; i += NTHR) dst[i] = src[i];
    }
    if (tid < H_) h_s[H_ + tid] = 0.f;       // h_{-1} lives in buf1

    if (tid < MVT) {
        // ================= matvec / update threads =================
        const int y = tid & 3;               // 0..3 ; gates y and y+4
        const int j = tid >> 2;              // hidden unit 0..63
        const int base = lane & ~3;          // lane of y==0 in this 4-lane group

        // Register-resident Wh columns for gates glo = y*64+j, ghi = (y+4)*64+j
        u64 wlo[H_ / 2], whi[H_ / 2];
        {
            const int glo = y * H_ + j;
#pragma unroll
            for (int k2 = 0; k2 < H_ / 2; ++k2)
                wlo[k2] = pack2(Wh[(2 * k2) * G7 + glo], Wh[(2 * k2 + 1) * G7 + glo]);
            if (y < 3) {
                const int ghi = (y + 4) * H_ + j;
#pragma unroll
                for (int k2 = 0; k2 < H_ / 2; ++k2)
                    whi[k2] = pack2(Wh[(2 * k2) * G7 + ghi], Wh[(2 * k2 + 1) * G7 + ghi]);
            } else {
#pragma unroll
                for (int k2 = 0; k2 < H_ / 2; ++k2) whi[k2] = 0ull;
            }
        }

        float c = 0.f, cbv = 0.f;            // valid in y==0 lanes
        // branch-free lo activation constants: y==2 -> tanh, else sigmoid
        const float kmul = (y == 2) ? -2.0f : -1.0f;
        const float bnum = (y == 2) ?  2.0f :  1.0f;
        const float aoff = (y == 2) ? -1.0f :  0.0f;

        __syncthreads();

        int   ev  = ev_row[0];
        float dtv = dt_row[1];

        for (int t = 0; t < T_; ++t) {
            const int   ev_next = ev_row[(t + 1 < T_) ? (t + 1) : (T_ - 1)];
            const float dt_next = dt_row[(t + 2 < TP2) ? (t + 2) : (TP2 - 1)];

            const float* hr = h_s + ((t & 1) ? 0 : H_);   // h_{t-1}
            float*       hw = h_s + ((t & 1) ? H_ : 0);   // h_t

            // ---- two dot products sharing one h read ----
            const float2 pre = pretab_s[ev * MVT + tid];
            const ulonglong2* h2 = (const ulonglong2*)hr;
            u64 aL0 = pack2(pre.x, 0.f), aL1 = 0ull;
            u64 aH0 = pack2(pre.y, 0.f), aH1 = 0ull;
#pragma unroll
            for (int k4 = 0; k4 < 16; ++k4) {
                ulonglong2 hp = h2[k4];
                aL0 = ffma2_(hp.x, wlo[2 * k4],     aL0);
                aL1 = ffma2_(hp.y, wlo[2 * k4 + 1], aL1);
                aH0 = ffma2_(hp.x, whi[2 * k4],     aH0);
                aH1 = ffma2_(hp.y, whi[2 * k4 + 1], aH1);
            }
            float2 rL = unpack2(fadd2_(aL0, aL1));
            float2 rH = unpack2(fadd2_(aH0, aH1));
            const float gLo = rL.x + rL.y;
            const float gHi = rH.x + rH.y;

            // ---- activations ----
            // lo: i,f,o sigmoid; z tanh (branch-free via constants)
            float aLo = __fdividef(bnum, 1.0f + __expf(kmul * gLo)) + aoff;
            // hi: ib,fb sigmoid (y 0,1); y==2: e = exp(-delta*dt)
            float aHi = __fdividef(1.0f, 1.0f + __expf(-gHi));
            if (y == 2) aHi = __expf(-dtv * fast_softplus(gHi));

            // ---- gather 7 gates of unit j within the 4-lane group ----
            const float fv  = __shfl_sync(0xffffffffu, aLo, base + 1);
            const float zv  = __shfl_sync(0xffffffffu, aLo, base + 2);
            const float ov  = __shfl_sync(0xffffffffu, aLo, base + 3);
            const float fbv = __shfl_sync(0xffffffffu, aHi, base + 1);
            const float ev_ = __shfl_sync(0xffffffffu, aHi, base + 2);
            // iv = aLo (y0 local), ibv = aHi (y0 local)

            // ---- cell update (meaningful in y==0 lanes) ----
            const float ci  = fmaf(fv, c, aLo * zv);
            const float cbi = fmaf(fbv, cbv, aHi * zv);
            const float cn  = fmaf(ci - cbi, ev_, cbi);
            c   = cn;
            cbv = cbi;
            const float hn = ov * fast_tanh(cn);
            if (y == 0) hw[j] = hn;

            __syncthreads();
            ev  = ev_next;
            dtv = dt_next;
        }
    } else {
        // ================= out-proj threads (tid 256..319): 2 logits each =================
        const int ot = tid - MVT;            // 0..63, active < 50
        const bool on = (ot < 50);
        const int k0 = 2 * ot, k1 = 2 * ot + 1;
        u64 oe0[H_ / 2], oe1[H_ / 2];
        if (on) {
#pragma unroll
            for (int i = 0; i < H_ / 2; ++i) {
                oe0[i] = pack2(out_emb[k0 * H_ + 2 * i], out_emb[k0 * H_ + 2 * i + 1]);
                oe1[i] = pack2(out_emb[k1 * H_ + 2 * i], out_emb[k1 * H_ + 2 * i + 1]);
            }
        } else {
#pragma unroll
            for (int i = 0; i < H_ / 2; ++i) { oe0[i] = 0ull; oe1[i] = 0ull; }
        }

        __syncthreads();

        for (int t = 0; t < T_; ++t) {
            const float* hr = h_s + ((t & 1) ? 0 : H_);   // h_{t-1}
            if (t > 0) {
                const ulonglong2* hp2 = (const ulonglong2*)hr;
                u64 s00 = 0ull, s01 = 0ull, s10 = 0ull, s11 = 0ull;
#pragma unroll
                for (int i = 0; i < 16; ++i) {
                    ulonglong2 hv = hp2[i];
                    s00 = ffma2_(hv.x, oe0[2 * i],     s00);
                    s01 = ffma2_(hv.y, oe0[2 * i + 1], s01);
                    s10 = ffma2_(hv.x, oe1[2 * i],     s10);
                    s11 = ffma2_(hv.y, oe1[2 * i + 1], s11);
                }
                float2 r0 = unpack2(fadd2_(s00, s01));
                float2 r1 = unpack2(fadd2_(s10, s11));
                if (on) {
                    float* orow = out_row + (size_t)(t - 1) * K_;
                    orow[k0] = fast_softplus(r0.x + r0.y);
                    orow[k1] = fast_softplus(r1.x + r1.y);
                }
            }
            __syncthreads();
        }

        // ---- drain: final output row from h_{T-1} (buf0, (T-1)&1==0) ----
        {
            const ulonglong2* hp2 = (const ulonglong2*)h_s;
            u64 s00 = 0ull, s01 = 0ull, s10 = 0ull, s11 = 0ull;
#pragma unroll
            for (int i = 0; i < 16; ++i) {
                ulonglong2 hv = hp2[i];
                s00 = ffma2_(hv.x, oe0[2 * i],     s00);
                s01 = ffma2_(hv.y, oe0[2 * i + 1], s01);
                s10 = ffma2_(hv.x, oe1[2 * i],     s10);
                s11 = ffma2_(hv.y, oe1[2 * i + 1], s11);
            }
            float2 r0 = unpack2(fadd2_(s00, s01));
            float2 r1 = unpack2(fadd2_(s10, s11));
            if (on) {
                float* orow = out_row + (size_t)(T_ - 1) * K_;
                orow[k0] = fast_softplus(r0.x + r0.y);
                orow[k1] = fast_softplus(r1.x + r1.y);
            }
        }
    }
}

extern "C" void kernel_launch(void* const* d_in, const int* in_sizes, int n_in,
                              void* d_out, int out_size) {
    const int*   ev   = (const int*)  d_in[0];
    const float* dt   = (const float*)d_in[1];
    const float* iemb = (const float*)d_in[2];
    const float* Wx   = (const float*)d_in[3];
    const float* Wh   = (const float*)d_in[4];
    const float* bias = (const float*)d_in[5];
    const float* oemb = (const float*)d_in[6];
    float* out = (float*)d_out;

    const size_t smem_bytes = (size_t)(2 * KE * MVT + 2 * H_ + 16) * sizeof(float);
    cudaFuncSetAttribute(scan_kernel, cudaFuncAttributeMaxDynamicSharedMemorySize,
                         (int)smem_bytes);

    build_pretab<<<KE, MVT>>>(iemb, Wx, bias);
    scan_kernel<<<B_, NTHR, smem_bytes>>>(ev, dt, Wh, oemb, out);
}